// round 5
// baseline (speedup 1.0000x reference)
#include <cuda_runtime.h>
#include <cstdint>

// Problem constants (fixed by the dataset)
#define BB 4096
#define SS 50
#define DD 768
#define UU 768
#define QQ 200
#define QP 256   // Q padded to 256 so all GEMM dims divide evenly

// Scratch (device globals: allocation-free per harness rules)
__device__ float g_W1p[QP * UU];   // W1 zero-padded to [256, 768]
__device__ float g_b1p[QP];        // b1 zero-padded to [256]
__device__ float g_W2p[DD * QP];   // W2 zero-padded to [768, 256]
__device__ float g_qp[BB * QP];    // relu(ue @ W1p^T + b1p), stride 256
__device__ float g_w[BB * DD];     // tanh(q @ W2p^T + b2)

// ---------------------------------------------------------------------------
// Pad W1 [200,768]->[256,768], b1 [200]->[256], W2 [768,200]->[768,256]
// ---------------------------------------------------------------------------
__global__ void pad_weights(const float* __restrict__ W1, const float* __restrict__ b1,
                            const float* __restrict__ W2,
                            float* __restrict__ W1p, float* __restrict__ b1p,
                            float* __restrict__ W2p)
{
    int i = blockIdx.x * blockDim.x + threadIdx.x;
    if (i < QP * UU) {
        W1p[i] = (i < QQ * UU) ? W1[i] : 0.f;
        int cidx = i & (QP - 1);
        W2p[i] = (cidx < QQ) ? W2[(i >> 8) * QQ + cidx] : 0.f;
    }
    if (i < QP) b1p[i] = (i < QQ) ? b1[i] : 0.f;
}

// ---------------------------------------------------------------------------
// GEMM: C[m][n] = act( sum_k A[m][k] * B[n][k] + bias[n] )
// BM=32, BN=32, BK=16, 128 threads, TM=4 x TN=2 microtile (8 out/thread).
// Small tiles on purpose: maximize CTA count (grids 1024 / 3072) so these
// latency-bound GEMMs get 7-8 CTAs/SM. Double-buffered smem, 1 sync/iter.
// ACT: 0 = relu, 1 = tanh
// ---------------------------------------------------------------------------
#define GBM 32
#define GBN 32
#define GBK 16

template <int ACT>
__global__ void __launch_bounds__(128, 8)
gemm_db(const float* __restrict__ A, const float* __restrict__ B,
        const float* __restrict__ bias, float* __restrict__ C,
        int M, int N, int K)
{
    __shared__ float As[2][GBK][GBM];
    __shared__ float Bs[2][GBK][GBN];

    const int m0 = blockIdx.x * GBM;
    const int n0 = blockIdx.y * GBN;
    const int t  = threadIdx.x;
    const int tx = t & 15;    // N dir: 16 * TN=2 = 32
    const int ty = t >> 4;    // M dir:  8 * TM=4 = 32

    // Tile-load mapping: each thread owns 1 float4 of A and 1 of B.
    const int ml = t >> 2;          // 0..31
    const int kq = (t & 3) * 4;     // 0,4,8,12

    const float* aptr = A + (size_t)(m0 + ml) * K + kq;
    const float* bptr = B + (size_t)(n0 + ml) * K + kq;

    float acc[4][2] = {};

    // Prologue: tile 0 -> buf 0
    float4 ar = *reinterpret_cast<const float4*>(aptr);
    float4 br = *reinterpret_cast<const float4*>(bptr);
    As[0][kq + 0][ml] = ar.x; As[0][kq + 1][ml] = ar.y;
    As[0][kq + 2][ml] = ar.z; As[0][kq + 3][ml] = ar.w;
    Bs[0][kq + 0][ml] = br.x; Bs[0][kq + 1][ml] = br.y;
    Bs[0][kq + 2][ml] = br.z; Bs[0][kq + 3][ml] = br.w;
    __syncthreads();

    const int kIters = K / GBK;
#pragma unroll 1
    for (int it = 0; it < kIters; it++) {
        const int cur = it & 1;
        if (it + 1 < kIters) {
            const int off = (it + 1) * GBK;
            ar = *reinterpret_cast<const float4*>(aptr + off);
            br = *reinterpret_cast<const float4*>(bptr + off);
        }
#pragma unroll
        for (int k = 0; k < GBK; k++) {
            float4 a = *reinterpret_cast<const float4*>(&As[cur][k][ty * 4]);
            float2 b = *reinterpret_cast<const float2*>(&Bs[cur][k][tx * 2]);
            acc[0][0] += a.x * b.x; acc[0][1] += a.x * b.y;
            acc[1][0] += a.y * b.x; acc[1][1] += a.y * b.y;
            acc[2][0] += a.z * b.x; acc[2][1] += a.z * b.y;
            acc[3][0] += a.w * b.x; acc[3][1] += a.w * b.y;
        }
        if (it + 1 < kIters) {
            const int nxt = cur ^ 1;
            As[nxt][kq + 0][ml] = ar.x; As[nxt][kq + 1][ml] = ar.y;
            As[nxt][kq + 2][ml] = ar.z; As[nxt][kq + 3][ml] = ar.w;
            Bs[nxt][kq + 0][ml] = br.x; Bs[nxt][kq + 1][ml] = br.y;
            Bs[nxt][kq + 2][ml] = br.z; Bs[nxt][kq + 3][ml] = br.w;
        }
        __syncthreads();
    }

    // Epilogue: bias + activation (dims padded -> no bounds checks)
#pragma unroll
    for (int i = 0; i < 4; i++) {
        int m = m0 + ty * 4 + i;
#pragma unroll
        for (int j = 0; j < 2; j++) {
            int n = n0 + tx * 2 + j;
            float v = acc[i][j] + bias[n];
            v = (ACT == 0) ? fmaxf(v, 0.f) : tanhf(v);
            C[(size_t)m * N + n] = v;
        }
    }
}

// ---------------------------------------------------------------------------
// Attention kernel v2: one CTA (512 threads) per batch row, NO c smem cache.
//
// R4 ncu: smem-tile version held DRAM at 67.9% because 150KB smem forced
// 1 CTA/SM (occ 24%) and the load->softmax->store phases serialized per SM.
// Here: pass 1 streams c once (normal caching -> lines land in L2, working
// set ~3*148*150KB = 67MB < 126MB L2); pass 2 re-reads via __ldcs (evict-
// first, last use) and writes via __stcs (streaming, don't evict the reuse
// data). 3 CTAs/SM -> phases from different CTAs overlap, HBM stays busy.
// ---------------------------------------------------------------------------
__global__ void __launch_bounds__(512, 3)
attn_kernel(const float* __restrict__ c, const float* __restrict__ w,
            float* __restrict__ out)
{
    __shared__ float attn_s[64];

    const int tid  = threadIdx.x;
    const int wi   = tid >> 5;
    const int lane = tid & 31;
    const int b    = blockIdx.x;

    // w row slice in registers (lane-invariant across the rows this warp does)
    const float4* w4 = reinterpret_cast<const float4*>(w + (size_t)b * DD);
    float4 wr[6];
#pragma unroll
    for (int i = 0; i < 6; i++) wr[i] = w4[lane + i * 32];

    const float4* c4 = reinterpret_cast<const float4*>(c + (size_t)b * (SS * DD));

    // Pass 1: scores (c lines allocate in L2 for reuse in pass 2)
#pragma unroll 1
    for (int s = wi; s < SS; s += 16) {
        const float4* crow = c4 + s * (DD / 4);
        float acc = 0.f;
#pragma unroll
        for (int i = 0; i < 6; i++) {
            float4 cv = crow[lane + i * 32];
            acc += cv.x * wr[i].x + cv.y * wr[i].y + cv.z * wr[i].z + cv.w * wr[i].w;
        }
#pragma unroll
        for (int off = 16; off > 0; off >>= 1)
            acc += __shfl_xor_sync(0xFFFFFFFFu, acc, off);
        if (lane == 0) attn_s[s] = acc;
    }
    __syncthreads();

    // Softmax over S = 50 (warp 0)
    if (tid < 32) {
        float v0 = attn_s[lane];
        float v1 = (lane + 32 < SS) ? attn_s[lane + 32] : -1e30f;
        float m = fmaxf(v0, v1);
#pragma unroll
        for (int off = 16; off > 0; off >>= 1)
            m = fmaxf(m, __shfl_xor_sync(0xFFFFFFFFu, m, off));
        float e0 = __expf(v0 - m);
        float e1 = (lane + 32 < SS) ? __expf(v1 - m) : 0.f;
        float sum = e0 + e1;
#pragma unroll
        for (int off = 16; off > 0; off >>= 1)
            sum += __shfl_xor_sync(0xFFFFFFFFu, sum, off);
        float inv = 1.f / sum;
        attn_s[lane] = e0 * inv;
        if (lane + 32 < SS) attn_s[lane + 32] = e1 * inv;
    }
    __syncthreads();

    // Pass 2: out = c * attn. Re-read hits L2; evict-first on read,
    // streaming store on write.
    float4* o4 = reinterpret_cast<float4*>(out) + (size_t)b * (SS * DD / 4);
#pragma unroll 2
    for (int i = tid; i < SS * DD / 4; i += 512) {
        int s = i / (DD / 4);
        float a = attn_s[s];
        float4 v = __ldcs(&c4[i]);
        v.x *= a; v.y *= a; v.z *= a; v.w *= a;
        __stcs(&o4[i], v);
    }
}

// ---------------------------------------------------------------------------
extern "C" void kernel_launch(void* const* d_in, const int* in_sizes, int n_in,
                              void* d_out, int out_size)
{
    const float* c   = (const float*)d_in[0];   // [B,S,D]
    const float* ue  = (const float*)d_in[1];   // [B,U]
    const float* W1  = (const float*)d_in[2];   // [Q,U]
    const float* b1  = (const float*)d_in[3];   // [Q]
    const float* W2  = (const float*)d_in[4];   // [D,Q]
    const float* b2  = (const float*)d_in[5];   // [D]
    float* out = (float*)d_out;

    float *W1p, *b1p, *W2p, *qp, *wbuf;
    cudaGetSymbolAddress((void**)&W1p, g_W1p);
    cudaGetSymbolAddress((void**)&b1p, g_b1p);
    cudaGetSymbolAddress((void**)&W2p, g_W2p);
    cudaGetSymbolAddress((void**)&qp,  g_qp);
    cudaGetSymbolAddress((void**)&wbuf, g_w);

    // Pad weights (tiny)
    pad_weights<<<(QP * UU + 255) / 256, 256>>>(W1, b1, W2, W1p, b1p, W2p);

    // q = relu(ue @ W1p^T + b1p)   M=4096, N=256, K=768 -> grid 128x8 = 1024
    gemm_db<0><<<dim3(BB / GBM, QP / GBN), 128>>>(ue, W1p, b1p, qp, BB, QP, UU);
    // w = tanh(q @ W2p^T + b2)     M=4096, N=768, K=256 -> grid 128x24 = 3072
    gemm_db<1><<<dim3(BB / GBM, DD / GBN), 128>>>(qp, W2p, b2, wbuf, BB, DD, QP);
    // attention body
    attn_kernel<<<BB, 512>>>(c, wbuf, out);
}

// round 7
// speedup vs baseline: 1.0145x; 1.0145x over previous
#include <cuda_runtime.h>
#include <cstdint>

// Problem constants (fixed by the dataset)
#define BB 4096
#define SS 50
#define DD 768
#define UU 768
#define QQ 200
#define QP 256   // Q padded to 256 so all GEMM dims divide evenly

// Scratch (device globals: allocation-free per harness rules)
__device__ float g_W1p[QP * UU];   // W1 zero-padded to [256, 768]
__device__ float g_b1p[QP];        // b1 zero-padded to [256]
__device__ float g_W2p[DD * QP];   // W2 zero-padded to [768, 256]
__device__ float g_qp[BB * QP];    // relu(ue @ W1p^T + b1p), stride 256
__device__ float g_w[BB * DD];     // tanh(q @ W2p^T + b2)

// ---------------------------------------------------------------------------
// Pad W1 [200,768]->[256,768], b1 [200]->[256], W2 [768,200]->[768,256]
// ---------------------------------------------------------------------------
__global__ void pad_weights(const float* __restrict__ W1, const float* __restrict__ b1,
                            const float* __restrict__ W2,
                            float* __restrict__ W1p, float* __restrict__ b1p,
                            float* __restrict__ W2p)
{
    int i = blockIdx.x * blockDim.x + threadIdx.x;
    if (i < QP * UU) {
        W1p[i] = (i < QQ * UU) ? W1[i] : 0.f;
        int cidx = i & (QP - 1);
        W2p[i] = (cidx < QQ) ? W2[(i >> 8) * QQ + cidx] : 0.f;
    }
    if (i < QP) b1p[i] = (i < QQ) ? b1[i] : 0.f;
}

// ---------------------------------------------------------------------------
// Packed fp32x2 FMA (sm_100+). d = a*b + c elementwise on (lo,hi) pairs.
// 3-reg FFMA is rt=2/SMSP on B300 (half rate); fma.rn.f32x2 does 2 MAC/lane
// per instruction -> restores the 128 MAC/cyc/SM fp32 peak.
// ---------------------------------------------------------------------------
__device__ __forceinline__ unsigned long long fma2(unsigned long long a,
                                                   unsigned long long b,
                                                   unsigned long long c)
{
    unsigned long long d;
    asm("fma.rn.f32x2 %0, %1, %2, %3;" : "=l"(d) : "l"(a), "l"(b), "l"(c));
    return d;
}
__device__ __forceinline__ float pk_lo(unsigned long long v) {
    return __uint_as_float((unsigned)(v & 0xffffffffull));
}
__device__ __forceinline__ float pk_hi(unsigned long long v) {
    return __uint_as_float((unsigned)(v >> 32));
}

// ---------------------------------------------------------------------------
// GEMM: C[m][n] = act( sum_k A[m][k] * B[n][k] + bias[n] )
// A: [M,K] row-major, B: [N,K] row-major (x @ W^T pattern). Dims divide evenly.
// BM=64, BN=64, BK=16, 128 threads, 8x4 microtile, double-buffered smem.
// FMA2 trick: accumulators hold M-row PAIRS packed in 64-bit; A pairs come
// free from aligned LDS.128 of As[k][m]; B is stored DUPLICATED in smem
// (Bs2[k][2n]=Bs2[k][2n+1]=b) so (b,b) operands also come free from LDS.128.
// Inner loop per k: 4 LDS.128 + 16 FMA2 = 64 MAC.
// ACT: 0 = relu, 1 = tanh
// ---------------------------------------------------------------------------
#define GBM 64
#define GBN 64
#define GBK 16

template <int ACT>
__global__ void __launch_bounds__(128)
gemm_f32x2(const float* __restrict__ A, const float* __restrict__ B,
           const float* __restrict__ bias, float* __restrict__ C,
           int M, int N, int K)
{
    __shared__ __align__(16) float As [2][GBK][GBM];
    __shared__ __align__(16) float Bs2[2][GBK][2 * GBN];

    const int m0 = blockIdx.x * GBM;
    const int n0 = blockIdx.y * GBN;
    const int t  = threadIdx.x;
    const int tx = t & 15;    // N dir: 16 * TN=4 = 64
    const int ty = t >> 4;    // M dir:  8 * TM=8 = 64

    // Tile-load mapping: thread owns row lr (0..63) and k-chunks kc, kc+8.
    const int lr = t >> 1;          // 0..63
    const int kc = (t & 1) * 4;     // 0 or 4

    const float* aptr = A + (size_t)(m0 + lr) * K + kc;
    const float* bptr = B + (size_t)(n0 + lr) * K + kc;

    unsigned long long acc[4][4];   // [m-pair][n]; packed (m_even, m_odd)
#pragma unroll
    for (int i = 0; i < 4; i++)
#pragma unroll
        for (int j = 0; j < 4; j++) acc[i][j] = 0ull;   // (0.f, 0.f)

    float4 ar0, ar1, br0, br1;

    // Prologue: tile 0 -> buf 0
    ar0 = *reinterpret_cast<const float4*>(aptr);
    ar1 = *reinterpret_cast<const float4*>(aptr + 8);
    br0 = *reinterpret_cast<const float4*>(bptr);
    br1 = *reinterpret_cast<const float4*>(bptr + 8);
    {
        const float av[8] = {ar0.x, ar0.y, ar0.z, ar0.w, ar1.x, ar1.y, ar1.z, ar1.w};
        const float bv[8] = {br0.x, br0.y, br0.z, br0.w, br1.x, br1.y, br1.z, br1.w};
#pragma unroll
        for (int i = 0; i < 4; i++) {
            As[0][kc + i][lr]     = av[i];
            As[0][kc + 8 + i][lr] = av[4 + i];
            Bs2[0][kc + i][2 * lr]         = bv[i];
            Bs2[0][kc + i][2 * lr + 1]     = bv[i];
            Bs2[0][kc + 8 + i][2 * lr]     = bv[4 + i];
            Bs2[0][kc + 8 + i][2 * lr + 1] = bv[4 + i];
        }
    }
    __syncthreads();

    const int kIters = K / GBK;
#pragma unroll 1
    for (int it = 0; it < kIters; it++) {
        const int cur = it & 1;
        if (it + 1 < kIters) {
            const int off = (it + 1) * GBK;
            ar0 = *reinterpret_cast<const float4*>(aptr + off);
            ar1 = *reinterpret_cast<const float4*>(aptr + off + 8);
            br0 = *reinterpret_cast<const float4*>(bptr + off);
            br1 = *reinterpret_cast<const float4*>(bptr + off + 8);
        }
#pragma unroll
        for (int k = 0; k < GBK; k++) {
            // A m-pairs: (m0,m1),(m2,m3),(m4,m5),(m6,m7) — free via LDS.128
            ulonglong2 a01 = *reinterpret_cast<const ulonglong2*>(&As[cur][k][ty * 8]);
            ulonglong2 a23 = *reinterpret_cast<const ulonglong2*>(&As[cur][k][ty * 8 + 4]);
            // B dup-pairs: (b0,b0),(b1,b1),(b2,b2),(b3,b3)
            ulonglong2 b01 = *reinterpret_cast<const ulonglong2*>(&Bs2[cur][k][tx * 8]);
            ulonglong2 b23 = *reinterpret_cast<const ulonglong2*>(&Bs2[cur][k][tx * 8 + 4]);

            acc[0][0] = fma2(a01.x, b01.x, acc[0][0]);
            acc[0][1] = fma2(a01.x, b01.y, acc[0][1]);
            acc[0][2] = fma2(a01.x, b23.x, acc[0][2]);
            acc[0][3] = fma2(a01.x, b23.y, acc[0][3]);
            acc[1][0] = fma2(a01.y, b01.x, acc[1][0]);
            acc[1][1] = fma2(a01.y, b01.y, acc[1][1]);
            acc[1][2] = fma2(a01.y, b23.x, acc[1][2]);
            acc[1][3] = fma2(a01.y, b23.y, acc[1][3]);
            acc[2][0] = fma2(a23.x, b01.x, acc[2][0]);
            acc[2][1] = fma2(a23.x, b01.y, acc[2][1]);
            acc[2][2] = fma2(a23.x, b23.x, acc[2][2]);
            acc[2][3] = fma2(a23.x, b23.y, acc[2][3]);
            acc[3][0] = fma2(a23.y, b01.x, acc[3][0]);
            acc[3][1] = fma2(a23.y, b01.y, acc[3][1]);
            acc[3][2] = fma2(a23.y, b23.x, acc[3][2]);
            acc[3][3] = fma2(a23.y, b23.y, acc[3][3]);
        }
        if (it + 1 < kIters) {
            const int nxt = cur ^ 1;
            const float av[8] = {ar0.x, ar0.y, ar0.z, ar0.w, ar1.x, ar1.y, ar1.z, ar1.w};
            const float bv[8] = {br0.x, br0.y, br0.z, br0.w, br1.x, br1.y, br1.z, br1.w};
#pragma unroll
            for (int i = 0; i < 4; i++) {
                As[nxt][kc + i][lr]     = av[i];
                As[nxt][kc + 8 + i][lr] = av[4 + i];
                Bs2[nxt][kc + i][2 * lr]         = bv[i];
                Bs2[nxt][kc + i][2 * lr + 1]     = bv[i];
                Bs2[nxt][kc + 8 + i][2 * lr]     = bv[4 + i];
                Bs2[nxt][kc + 8 + i][2 * lr + 1] = bv[4 + i];
            }
        }
        __syncthreads();
    }

    // Epilogue: bias + activation; n-contiguous float4 stores per m row.
    const float4 bias4 = *reinterpret_cast<const float4*>(bias + n0 + tx * 4);
#pragma unroll
    for (int mp = 0; mp < 4; mp++) {
        float lo[4], hi[4];
#pragma unroll
        for (int j = 0; j < 4; j++) { lo[j] = pk_lo(acc[mp][j]); hi[j] = pk_hi(acc[mp][j]); }
        const float bb[4] = {bias4.x, bias4.y, bias4.z, bias4.w};
        float4 vlo, vhi;
        float* plo = &vlo.x; float* phi = &vhi.x;
#pragma unroll
        for (int j = 0; j < 4; j++) {
            float a = lo[j] + bb[j];
            float b = hi[j] + bb[j];
            plo[j] = (ACT == 0) ? fmaxf(a, 0.f) : tanhf(a);
            phi[j] = (ACT == 0) ? fmaxf(b, 0.f) : tanhf(b);
        }
        int m_lo = m0 + ty * 8 + 2 * mp;
        *reinterpret_cast<float4*>(C + (size_t)m_lo * N + n0 + tx * 4)       = vlo;
        *reinterpret_cast<float4*>(C + (size_t)(m_lo + 1) * N + n0 + tx * 4) = vhi;
    }
}

// ---------------------------------------------------------------------------
// Attention kernel (R4 version, 227us, DRAM 68%): one CTA (512 thr) per batch
// row; c cached in smem via fused LDG->STS->dot; c read from HBM exactly once.
// ---------------------------------------------------------------------------
#define ATTN_SMEM_BYTES 153856

__global__ void __launch_bounds__(512, 1)
attn_kernel(const float* __restrict__ c, const float* __restrict__ w,
            float* __restrict__ out)
{
    extern __shared__ __align__(16) unsigned char smem_raw[];
    float* attn_s = reinterpret_cast<float*>(smem_raw);
    float* c_s    = reinterpret_cast<float*>(smem_raw + 256);

    const int tid  = threadIdx.x;
    const int wi   = tid >> 5;
    const int lane = tid & 31;
    const int b    = blockIdx.x;

    const float4* w4 = reinterpret_cast<const float4*>(w + (size_t)b * DD);
    float4 wr[6];
#pragma unroll
    for (int i = 0; i < 6; i++) wr[i] = __ldg(&w4[lane + i * 32]);

    const float4* c4g = reinterpret_cast<const float4*>(c + (size_t)b * (SS * DD));
    float4* c4s = reinterpret_cast<float4*>(c_s);

#pragma unroll 1
    for (int s = wi; s < SS; s += 16) {
        const float4* crow = c4g + s * (DD / 4);
        float4*       srow = c4s + s * (DD / 4);
        float acc = 0.f;
#pragma unroll
        for (int i = 0; i < 6; i++) {
            float4 cv = crow[lane + i * 32];
            srow[lane + i * 32] = cv;
            acc += cv.x * wr[i].x + cv.y * wr[i].y + cv.z * wr[i].z + cv.w * wr[i].w;
        }
#pragma unroll
        for (int off = 16; off > 0; off >>= 1)
            acc += __shfl_xor_sync(0xFFFFFFFFu, acc, off);
        if (lane == 0) attn_s[s] = acc;
    }
    __syncthreads();

    if (tid < 32) {
        float v0 = attn_s[lane];
        float v1 = (lane + 32 < SS) ? attn_s[lane + 32] : -1e30f;
        float m = fmaxf(v0, v1);
#pragma unroll
        for (int off = 16; off > 0; off >>= 1)
            m = fmaxf(m, __shfl_xor_sync(0xFFFFFFFFu, m, off));
        float e0 = __expf(v0 - m);
        float e1 = (lane + 32 < SS) ? __expf(v1 - m) : 0.f;
        float sum = e0 + e1;
#pragma unroll
        for (int off = 16; off > 0; off >>= 1)
            sum += __shfl_xor_sync(0xFFFFFFFFu, sum, off);
        float inv = 1.f / sum;
        attn_s[lane] = e0 * inv;
        if (lane + 32 < SS) attn_s[lane + 32] = e1 * inv;
    }
    __syncthreads();

    float4* o4 = reinterpret_cast<float4*>(out) + (size_t)b * (SS * DD / 4);
#pragma unroll 4
    for (int i = tid; i < SS * DD / 4; i += 512) {
        int s = i / (DD / 4);
        float a = attn_s[s];
        float4 v = c4s[i];
        v.x *= a; v.y *= a; v.z *= a; v.w *= a;
        o4[i] = v;
    }
}

// ---------------------------------------------------------------------------
extern "C" void kernel_launch(void* const* d_in, const int* in_sizes, int n_in,
                              void* d_out, int out_size)
{
    const float* c   = (const float*)d_in[0];   // [B,S,D]
    const float* ue  = (const float*)d_in[1];   // [B,U]
    const float* W1  = (const float*)d_in[2];   // [Q,U]
    const float* b1  = (const float*)d_in[3];   // [Q]
    const float* W2  = (const float*)d_in[4];   // [D,Q]
    const float* b2  = (const float*)d_in[5];   // [D]
    float* out = (float*)d_out;

    float *W1p, *b1p, *W2p, *qp, *wbuf;
    cudaGetSymbolAddress((void**)&W1p, g_W1p);
    cudaGetSymbolAddress((void**)&b1p, g_b1p);
    cudaGetSymbolAddress((void**)&W2p, g_W2p);
    cudaGetSymbolAddress((void**)&qp,  g_qp);
    cudaGetSymbolAddress((void**)&wbuf, g_w);

    cudaFuncSetAttribute(attn_kernel,
                         cudaFuncAttributeMaxDynamicSharedMemorySize,
                         ATTN_SMEM_BYTES);

    // Pad weights (tiny)
    pad_weights<<<(QP * UU + 255) / 256, 256>>>(W1, b1, W2, W1p, b1p, W2p);

    // q = relu(ue @ W1p^T + b1p)   M=4096, N=256, K=768 -> grid 64x4 = 256
    gemm_f32x2<0><<<dim3(BB / GBM, QP / GBN), 128>>>(ue, W1p, b1p, qp, BB, QP, UU);
    // w = tanh(q @ W2p^T + b2)     M=4096, N=768, K=256 -> grid 64x12 = 768
    gemm_f32x2<1><<<dim3(BB / GBM, DD / GBN), 128>>>(qp, W2p, b2, wbuf, BB, DD, QP);
    // attention body
    attn_kernel<<<BB, 512, ATTN_SMEM_BYTES>>>(c, wbuf, out);
}

// round 9
// speedup vs baseline: 1.1838x; 1.1670x over previous
#include <cuda_runtime.h>
#include <cstdint>

// Problem constants (fixed by the dataset)
#define BB 4096
#define SS 50
#define DD 768
#define UU 768
#define QQ 200
#define QP 256   // Q padded to 256 so all GEMM dims divide evenly

// Scratch (device globals: allocation-free per harness rules)
__device__ float g_W1p[QP * UU];   // W1 zero-padded to [256, 768]
__device__ float g_b1p[QP];        // b1 zero-padded to [256]
__device__ float g_W2p[DD * QP];   // W2 zero-padded to [768, 256]
__device__ float g_qp[BB * QP];    // relu(ue @ W1p^T + b1p), stride 256
__device__ float g_w[BB * DD];     // tanh(q @ W2p^T + b2)

// ---------------------------------------------------------------------------
// Pad W1 [200,768]->[256,768], b1 [200]->[256], W2 [768,200]->[768,256]
// ---------------------------------------------------------------------------
__global__ void pad_weights(const float* __restrict__ W1, const float* __restrict__ b1,
                            const float* __restrict__ W2,
                            float* __restrict__ W1p, float* __restrict__ b1p,
                            float* __restrict__ W2p)
{
    int i = blockIdx.x * blockDim.x + threadIdx.x;
    if (i < QP * UU) {
        W1p[i] = (i < QQ * UU) ? W1[i] : 0.f;
        int cidx = i & (QP - 1);
        W2p[i] = (cidx < QQ) ? W2[(i >> 8) * QQ + cidx] : 0.f;
    }
    if (i < QP) b1p[i] = (i < QQ) ? b1[i] : 0.f;
}

// ---------------------------------------------------------------------------
// GEMM (R4 config — best measured): C[m][n] = act( A[m,:]·B[n,:] + bias[n] )
// BM=32, BN=64, BK=16, 128 threads, 4x4 microtile, double-buffered smem,
// one __syncthreads per K-iter. Grids 512 / 1536.
// ACT: 0 = relu, 1 = tanh
// ---------------------------------------------------------------------------
#define GBM 32
#define GBN 64
#define GBK 16

template <int ACT>
__global__ void __launch_bounds__(128, 8)
gemm_db(const float* __restrict__ A, const float* __restrict__ B,
        const float* __restrict__ bias, float* __restrict__ C,
        int M, int N, int K)
{
    __shared__ float As[2][GBK][GBM];
    __shared__ float Bs[2][GBK][GBN];

    const int m0 = blockIdx.x * GBM;
    const int n0 = blockIdx.y * GBN;
    const int t  = threadIdx.x;
    const int tx = t & 15;    // N dir: 16 * TN=4 = 64
    const int ty = t >> 4;    // M dir:  8 * TM=4 = 32

    const int ml = t >> 2;          // 0..31
    const int kq = (t & 3) * 4;     // 0,4,8,12

    const float* aptr  = A + (size_t)(m0 + ml) * K + kq;
    const float* bptr0 = B + (size_t)(n0 + ml) * K + kq;
    const float* bptr1 = B + (size_t)(n0 + ml + 32) * K + kq;

    float acc[4][4] = {};

    float4 ar  = *reinterpret_cast<const float4*>(aptr);
    float4 br0 = *reinterpret_cast<const float4*>(bptr0);
    float4 br1 = *reinterpret_cast<const float4*>(bptr1);
    As[0][kq + 0][ml] = ar.x;  As[0][kq + 1][ml] = ar.y;
    As[0][kq + 2][ml] = ar.z;  As[0][kq + 3][ml] = ar.w;
    Bs[0][kq + 0][ml] = br0.x; Bs[0][kq + 1][ml] = br0.y;
    Bs[0][kq + 2][ml] = br0.z; Bs[0][kq + 3][ml] = br0.w;
    Bs[0][kq + 0][ml + 32] = br1.x; Bs[0][kq + 1][ml + 32] = br1.y;
    Bs[0][kq + 2][ml + 32] = br1.z; Bs[0][kq + 3][ml + 32] = br1.w;
    __syncthreads();

    const int kIters = K / GBK;
#pragma unroll 1
    for (int it = 0; it < kIters; it++) {
        const int cur = it & 1;
        if (it + 1 < kIters) {
            const int off = (it + 1) * GBK;
            ar  = *reinterpret_cast<const float4*>(aptr  + off);
            br0 = *reinterpret_cast<const float4*>(bptr0 + off);
            br1 = *reinterpret_cast<const float4*>(bptr1 + off);
        }
#pragma unroll
        for (int k = 0; k < GBK; k++) {
            float4 a = *reinterpret_cast<const float4*>(&As[cur][k][ty * 4]);
            float4 b = *reinterpret_cast<const float4*>(&Bs[cur][k][tx * 4]);
            acc[0][0] += a.x * b.x; acc[0][1] += a.x * b.y;
            acc[0][2] += a.x * b.z; acc[0][3] += a.x * b.w;
            acc[1][0] += a.y * b.x; acc[1][1] += a.y * b.y;
            acc[1][2] += a.y * b.z; acc[1][3] += a.y * b.w;
            acc[2][0] += a.z * b.x; acc[2][1] += a.z * b.y;
            acc[2][2] += a.z * b.z; acc[2][3] += a.z * b.w;
            acc[3][0] += a.w * b.x; acc[3][1] += a.w * b.y;
            acc[3][2] += a.w * b.z; acc[3][3] += a.w * b.w;
        }
        if (it + 1 < kIters) {
            const int nxt = cur ^ 1;
            As[nxt][kq + 0][ml] = ar.x;  As[nxt][kq + 1][ml] = ar.y;
            As[nxt][kq + 2][ml] = ar.z;  As[nxt][kq + 3][ml] = ar.w;
            Bs[nxt][kq + 0][ml] = br0.x; Bs[nxt][kq + 1][ml] = br0.y;
            Bs[nxt][kq + 2][ml] = br0.z; Bs[nxt][kq + 3][ml] = br0.w;
            Bs[nxt][kq + 0][ml + 32] = br1.x; Bs[nxt][kq + 1][ml + 32] = br1.y;
            Bs[nxt][kq + 2][ml + 32] = br1.z; Bs[nxt][kq + 3][ml + 32] = br1.w;
        }
        __syncthreads();
    }

#pragma unroll
    for (int i = 0; i < 4; i++) {
        int m = m0 + ty * 4 + i;
#pragma unroll
        for (int j = 0; j < 4; j++) {
            int n = n0 + tx * 4 + j;
            float v = acc[i][j] + bias[n];
            v = (ACT == 0) ? fmaxf(v, 0.f) : tanhf(v);
            C[(size_t)m * N + n] = v;
        }
    }
}

// ---------------------------------------------------------------------------
// Attention kernel v4 ("half-cache"): one CTA (256 thr) per batch row.
// Rows 0..24 cached in smem (75 KB -> 2 CTAs/SM); rows 25..49 streamed for
// the dot (lines stay in L2; concurrent set ~22 MB << 126 MB L2) and re-read
// from L2 in phase 3. HBM traffic unchanged (c once, out once); 2 CTAs/SM
// lets independent CTAs' load/softmax/store phases overlap (R4's 1-CTA/SM
// version idled DRAM 32% on phase bubbles).
//
// SMEM: [0,256)        scores/attn (50 floats, padded)
//       [256,77056)    c rows 0..24 (25*768 floats = 75 KB)
// ---------------------------------------------------------------------------
#define ATTN_SMEM_BYTES 77056
#define RCACHE 25   // rows cached in smem

__global__ void __launch_bounds__(256, 2)
attn_kernel(const float* __restrict__ c, const float* __restrict__ w,
            float* __restrict__ out)
{
    extern __shared__ __align__(16) unsigned char smem_raw[];
    float* attn_s = reinterpret_cast<float*>(smem_raw);
    float* c_s    = reinterpret_cast<float*>(smem_raw + 256);

    const int tid  = threadIdx.x;
    const int wi   = tid >> 5;      // 0..7
    const int lane = tid & 31;
    const int b    = blockIdx.x;

    // w row slice in registers (lane-invariant across rows)
    const float4* w4 = reinterpret_cast<const float4*>(w + (size_t)b * DD);
    float4 wr[6];
#pragma unroll
    for (int i = 0; i < 6; i++) wr[i] = __ldg(&w4[lane + i * 32]);

    const float4* c4g = reinterpret_cast<const float4*>(c + (size_t)b * (SS * DD));
    float4* c4s = reinterpret_cast<float4*>(c_s);

    // Phase 1a: rows 0..24 — stream to smem + dot
#pragma unroll 1
    for (int s = wi; s < RCACHE; s += 8) {
        const float4* crow = c4g + s * (DD / 4);
        float4*       srow = c4s + s * (DD / 4);
        float acc = 0.f;
#pragma unroll
        for (int i = 0; i < 6; i++) {
            float4 cv = crow[lane + i * 32];
            srow[lane + i * 32] = cv;
            acc += cv.x * wr[i].x + cv.y * wr[i].y + cv.z * wr[i].z + cv.w * wr[i].w;
        }
#pragma unroll
        for (int off = 16; off > 0; off >>= 1)
            acc += __shfl_xor_sync(0xFFFFFFFFu, acc, off);
        if (lane == 0) attn_s[s] = acc;
    }

    // Phase 1b: rows 25..49 — dot only; lines allocate in L2 for phase 3
#pragma unroll 1
    for (int s = RCACHE + wi; s < SS; s += 8) {
        const float4* crow = c4g + s * (DD / 4);
        float acc = 0.f;
#pragma unroll
        for (int i = 0; i < 6; i++) {
            float4 cv = crow[lane + i * 32];
            acc += cv.x * wr[i].x + cv.y * wr[i].y + cv.z * wr[i].z + cv.w * wr[i].w;
        }
#pragma unroll
        for (int off = 16; off > 0; off >>= 1)
            acc += __shfl_xor_sync(0xFFFFFFFFu, acc, off);
        if (lane == 0) attn_s[s] = acc;
    }
    __syncthreads();

    // Phase 2: softmax over S = 50 (warp 0)
    if (tid < 32) {
        float v0 = attn_s[lane];
        float v1 = (lane + 32 < SS) ? attn_s[lane + 32] : -1e30f;
        float m = fmaxf(v0, v1);
#pragma unroll
        for (int off = 16; off > 0; off >>= 1)
            m = fmaxf(m, __shfl_xor_sync(0xFFFFFFFFu, m, off));
        float e0 = __expf(v0 - m);
        float e1 = (lane + 32 < SS) ? __expf(v1 - m) : 0.f;
        float sum = e0 + e1;
#pragma unroll
        for (int off = 16; off > 0; off >>= 1)
            sum += __shfl_xor_sync(0xFFFFFFFFu, sum, off);
        float inv = 1.f / sum;
        attn_s[lane] = e0 * inv;
        if (lane + 32 < SS) attn_s[lane + 32] = e1 * inv;
    }
    __syncthreads();

    // Phase 3a: rows 0..24 from smem
    float4* o4 = reinterpret_cast<float4*>(out) + (size_t)b * (SS * DD / 4);
#pragma unroll 4
    for (int i = tid; i < RCACHE * (DD / 4); i += 256) {
        int s = i / (DD / 4);
        float a = attn_s[s];
        float4 v = c4s[i];
        v.x *= a; v.y *= a; v.z *= a; v.w *= a;
        o4[i] = v;
    }
    // Phase 3b: rows 25..49 re-read (L2 hit), multiply, store
    const int base = RCACHE * (DD / 4);
#pragma unroll 4
    for (int i = tid; i < (SS - RCACHE) * (DD / 4); i += 256) {
        int s = RCACHE + i / (DD / 4);
        float a = attn_s[s];
        float4 v = c4g[base + i];
        v.x *= a; v.y *= a; v.z *= a; v.w *= a;
        o4[base + i] = v;
    }
}

// ---------------------------------------------------------------------------
extern "C" void kernel_launch(void* const* d_in, const int* in_sizes, int n_in,
                              void* d_out, int out_size)
{
    const float* c   = (const float*)d_in[0];   // [B,S,D]
    const float* ue  = (const float*)d_in[1];   // [B,U]
    const float* W1  = (const float*)d_in[2];   // [Q,U]
    const float* b1  = (const float*)d_in[3];   // [Q]
    const float* W2  = (const float*)d_in[4];   // [D,Q]
    const float* b2  = (const float*)d_in[5];   // [D]
    float* out = (float*)d_out;

    float *W1p, *b1p, *W2p, *qp, *wbuf;
    cudaGetSymbolAddress((void**)&W1p, g_W1p);
    cudaGetSymbolAddress((void**)&b1p, g_b1p);
    cudaGetSymbolAddress((void**)&W2p, g_W2p);
    cudaGetSymbolAddress((void**)&qp,  g_qp);
    cudaGetSymbolAddress((void**)&wbuf, g_w);

    cudaFuncSetAttribute(attn_kernel,
                         cudaFuncAttributeMaxDynamicSharedMemorySize,
                         ATTN_SMEM_BYTES);

    // Pad weights (tiny)
    pad_weights<<<(QP * UU + 255) / 256, 256>>>(W1, b1, W2, W1p, b1p, W2p);

    // q = relu(ue @ W1p^T + b1p)   M=4096, N=256, K=768 -> grid 128x4 = 512
    gemm_db<0><<<dim3(BB / GBM, QP / GBN), 128>>>(ue, W1p, b1p, qp, BB, QP, UU);
    // w = tanh(q @ W2p^T + b2)     M=4096, N=768, K=256 -> grid 128x12 = 1536
    gemm_db<1><<<dim3(BB / GBM, DD / GBN), 128>>>(qp, W2p, b2, wbuf, BB, DD, QP);
    // attention body: one CTA per batch row, half-cached
    attn_kernel<<<BB, 256, ATTN_SMEM_BYTES>>>(c, wbuf, out);
}